// round 3
// baseline (speedup 1.0000x reference)
#include <cuda_runtime.h>

// Problem constants
#define PP 12
#define BB 4
#define KSTEP 12
#define TE_DEPTH 168
#define NUM_CELLS 1024   // 32*32
#define PQ 24            // P + Q

// Output layout (tuple flattened, row-major each):
//  Y       (B,1,H,W,1)       4096   @ 0
//  x       (B,P,H,W,1)      49152   @ 4096
//  trans   (B,P,H,W,8,1)   393216   @ 53248
//  restart (B,P,H,W,1)      49152   @ 446464
//  results (B,P,H,W,1,13)  638976   @ 495616
#define OFF_Y    0
#define OFF_X    4096
#define OFF_T    53248
#define OFF_R    446464
#define OFF_RES  495616

// DIRS d: 0:(-1,-1) 1:(-1,0) 2:(-1,1) 3:(0,-1) 4:(0,1) 5:(1,-1) 6:(1,0) 7:(1,1)

__global__ __launch_bounds__(256, 1) void rwr_kernel(
    const float* __restrict__ X,
    const int*   __restrict__ TE,
    const float* __restrict__ Wt,   // (1192, 8)
    const float* __restrict__ Wr,   // (1192, 1)
    const float* __restrict__ Wb,   // (1192, 1)
    float*       __restrict__ out)
{
    const int bp    = blockIdx.x;       // 0..47
    const int b     = bp / PP;
    const int p     = bp % PP;
    const int tid   = threadIdx.x;      // 0..255
    const int h     = tid >> 3;         // row 0..31
    const int w0    = (tid & 7) << 2;   // col base 0,4,...,28
    const int cell0 = (h << 5) + w0;

    // tp: padded trans-prob planes for the one-time incoming-weight gather;
    //     reused later as the results staging buffer (9248 floats >= 6656).
    // xs: double-buffered x tile, rows 0..33 (plane row h -> row h+1),
    //     cols: [0..3] pad, cells at [4..35], pad [36..39]. Cells 16B-aligned.
    __shared__ __align__(16) float tp[8][34][34];   // 36992 B
    __shared__ __align__(16) float xs[2][34][40];   // 10880 B

    // ---- prefetch all globals up front (max MLP) ----
    const float4 xin = *reinterpret_cast<const float4*>(X + bp * NUM_CELLS + cell0);
    const int te_day  = TE[(b * PQ + p) * 2 + 0];
    const int te_hour = TE[(b * PQ + p) * 2 + 1];
    const int te = te_day * 24 + te_hour;            // < 168
    const int cr0 = TE_DEPTH + cell0;

    // per-cell W rows (float4-aligned: rows are 8 floats)
    float4 wtc_lo[4], wtc_hi[4];
    #pragma unroll
    for (int j = 0; j < 4; j++) {
        const float4* wrow = reinterpret_cast<const float4*>(Wt + (size_t)(cr0 + j) * 8);
        wtc_lo[j] = wrow[0];
        wtc_hi[j] = wrow[1];
    }
    const float4 wrc = *reinterpret_cast<const float4*>(Wr + cr0);  // 4 consecutive cells
    const float4 wbc = *reinterpret_cast<const float4*>(Wb + cr0);
    // te rows (broadcast)
    const float4* wte4 = reinterpret_cast<const float4*>(Wt + (size_t)te * 8);
    const float4 wte_lo = wte4[0];
    const float4 wte_hi = wte4[1];
    const float wr_te = Wr[te];
    const float wb_te = Wb[te];

    // ---- zero tp (borders must be 0) while loads are in flight ----
    {
        float4* tpf = reinterpret_cast<float4*>(&tp[0][0][0]);
        #pragma unroll
        for (int i = 0; i < 10; i++) {
            int idx = tid + i * 256;
            if (idx < 2312) tpf[idx] = make_float4(0.f, 0.f, 0.f, 0.f);
        }
    }
    // ---- zero only the READ borders of xs (rows 0,33 cols 3..36; cols 3,36 rows 1..32) ----
    #pragma unroll
    for (int i = tid; i < 272; i += 256) {
        if (i < 272) {
            int bufb = i / 136, j = i % 136;
            if      (j <  34) xs[bufb][0 ][3 + j]        = 0.f;
            else if (j <  68) xs[bufb][33][3 + (j - 34)] = 0.f;
            else if (j < 100) xs[bufb][1 + (j - 68) ][3] = 0.f;
            else if (j < 132) xs[bufb][1 + (j - 100)][36] = 0.f;
        }
    }

    // ---- per-cell softmax (8 dirs), sigmoid restart, bias ----
    const float xv_in[4] = {xin.x, xin.y, xin.z, xin.w};
    float tpv[4][8], restart[4], omr[4], bias[4];
    #pragma unroll
    for (int j = 0; j < 4; j++) {
        float lg[8];
        lg[0] = wte_lo.x + wtc_lo[j].x;  lg[1] = wte_lo.y + wtc_lo[j].y;
        lg[2] = wte_lo.z + wtc_lo[j].z;  lg[3] = wte_lo.w + wtc_lo[j].w;
        lg[4] = wte_hi.x + wtc_hi[j].x;  lg[5] = wte_hi.y + wtc_hi[j].y;
        lg[6] = wte_hi.z + wtc_hi[j].z;  lg[7] = wte_hi.w + wtc_hi[j].w;
        float e[8], s = 0.f;
        #pragma unroll
        for (int d = 0; d < 8; d++) { e[d] = __expf(lg[d]); s += e[d]; }  // logits ~±0.1, no max-sub needed
        const float inv_s = __fdividef(1.0f, s);
        #pragma unroll
        for (int d = 0; d < 8; d++) tpv[j][d] = e[d] * inv_s;

        const float rz = wr_te + ((const float*)&wrc)[j];
        restart[j] = __fdividef(1.0f, 1.0f + __expf(-rz));
        omr[j] = 1.0f - restart[j];
        bias[j] = (wb_te + ((const float*)&wbc)[j]) * xv_in[j];
    }

    // ---- static outputs: trans (2 float4/cell), restart (float4/thread) ----
    #pragma unroll
    for (int j = 0; j < 4; j++) {
        float4* t4 = reinterpret_cast<float4*>(out + OFF_T + (size_t)(bp * NUM_CELLS + cell0 + j) * 8);
        t4[0] = make_float4(tpv[j][0], tpv[j][1], tpv[j][2], tpv[j][3]);
        t4[1] = make_float4(tpv[j][4], tpv[j][5], tpv[j][6], tpv[j][7]);
    }
    *reinterpret_cast<float4*>(out + OFF_R + bp * NUM_CELLS + cell0) =
        make_float4(restart[0], restart[1], restart[2], restart[3]);

    __syncthreads();   // tp zero done before interior fill

    // fill tp planes (interior)
    #pragma unroll
    for (int j = 0; j < 4; j++)
        #pragma unroll
        for (int d = 0; d < 8; d++)
            tp[d][h + 1][w0 + 1 + j] = tpv[j][d];

    __syncthreads();   // tp filled + xs borders zeroed

    // incoming weight gather: w_in[j][d] = trans-prob channel d of neighbor (h+DR, w+DC)
    const int DR[8] = {-1,-1,-1, 0, 0, 1, 1, 1};
    const int DC[8] = {-1, 0, 1,-1, 1,-1, 0, 1};
    float w_in[4][8];
    #pragma unroll
    for (int j = 0; j < 4; j++)
        #pragma unroll
        for (int d = 0; d < 8; d++)
            w_in[j][d] = tp[d][h + 1 + DR[d]][w0 + j + 1 + DC[d]];

    // ---- iterate: one STS.128 + 9 LDS per thread per step ----
    float r[4][KSTEP + 1];
    float xv[4] = {xv_in[0], xv_in[1], xv_in[2], xv_in[3]};
    #pragma unroll
    for (int j = 0; j < 4; j++) r[j][0] = xv[j];

    #pragma unroll
    for (int k = 0; k < KSTEP; k++) {
        const int buf = k & 1;
        *reinterpret_cast<float4*>(&xs[buf][h + 1][4 + w0]) =
            make_float4(xv[0], xv[1], xv[2], xv[3]);
        __syncthreads();

        // 6-wide windows for rows h-1, h, h+1: cols w0-1 .. w0+4
        float vt[6], vm[6], vb[6];
        {
            float4 v;
            v = *reinterpret_cast<const float4*>(&xs[buf][h    ][4 + w0]);
            vt[0] = xs[buf][h    ][3 + w0]; vt[1] = v.x; vt[2] = v.y; vt[3] = v.z; vt[4] = v.w;
            vt[5] = xs[buf][h    ][8 + w0];
            v = *reinterpret_cast<const float4*>(&xs[buf][h + 1][4 + w0]);
            vm[0] = xs[buf][h + 1][3 + w0]; vm[1] = v.x; vm[2] = v.y; vm[3] = v.z; vm[4] = v.w;
            vm[5] = xs[buf][h + 1][8 + w0];
            v = *reinterpret_cast<const float4*>(&xs[buf][h + 2][4 + w0]);
            vb[0] = xs[buf][h + 2][3 + w0]; vb[1] = v.x; vb[2] = v.y; vb[3] = v.z; vb[4] = v.w;
            vb[5] = xs[buf][h + 2][8 + w0];
        }

        #pragma unroll
        for (int j = 0; j < 4; j++) {
            float a0 = vt[j]     * w_in[j][0];
            float a1 = vt[j + 1] * w_in[j][1];
            float a2 = vt[j + 2] * w_in[j][2];
            float a3 = vm[j]     * w_in[j][3];
            a0 = fmaf(vm[j + 2], w_in[j][4], a0);
            a1 = fmaf(vb[j],     w_in[j][5], a1);
            a2 = fmaf(vb[j + 1], w_in[j][6], a2);
            a3 = fmaf(vb[j + 2], w_in[j][7], a3);
            const float xt = (a0 + a1) + (a2 + a3);
            xv[j] = fmaf(omr[j], xt, fmaf(restart[j], xv[j], bias[j]));
            r[j][k + 1] = xv[j];
        }
    }

    // final state x + Y (coalesced float4)
    *reinterpret_cast<float4*>(out + OFF_X + bp * NUM_CELLS + cell0) =
        make_float4(xv[0], xv[1], xv[2], xv[3]);
    if (p == PP - 1)
        *reinterpret_cast<float4*>(out + OFF_Y + b * NUM_CELLS + cell0) =
            make_float4(xv[0], xv[1], xv[2], xv[3]);

    // ---- results dump: stage through tp, 2 halves of 512 cells ----
    float* stage = &tp[0][0][0];
    #pragma unroll
    for (int hf = 0; hf < 2; hf++) {
        // (tp last read pre-loop for hf=0; post-copy BAR below for hf=1)
        if ((h >> 4) == hf) {
            const int lc0 = cell0 - hf * 512;
            #pragma unroll
            for (int j = 0; j < 4; j++)
                #pragma unroll
                for (int k = 0; k <= KSTEP; k++)
                    stage[(lc0 + j) * 13 + k] = r[j][k];
        }
        __syncthreads();
        const float4* s4 = reinterpret_cast<const float4*>(stage);
        float4* o4 = reinterpret_cast<float4*>(
            out + OFF_RES + (size_t)bp * (NUM_CELLS * 13) + hf * (512 * 13));
        #pragma unroll
        for (int i = 0; i < 7; i++) {
            int idx = tid + i * 256;
            if (idx < 1664) o4[idx] = s4[idx];
        }
        if (hf == 0) __syncthreads();   // copy0 reads done before stage1 writes
    }
}

extern "C" void kernel_launch(void* const* d_in, const int* in_sizes, int n_in,
                              void* d_out, int out_size) {
    const float* X  = (const float*)d_in[0];
    const int*   TE = (const int*)d_in[1];
    const float* Wt = (const float*)d_in[2];
    const float* Wr = (const float*)d_in[3];
    const float* Wb = (const float*)d_in[4];
    float* out = (float*)d_out;
    rwr_kernel<<<BB * PP, 256>>>(X, TE, Wt, Wr, Wb, out);
}

// round 4
// speedup vs baseline: 1.1797x; 1.1797x over previous
#include <cuda_runtime.h>

// Problem constants
#define PP 12
#define BB 4
#define KSTEP 12
#define TE_DEPTH 168
#define NUM_CELLS 1024   // 32*32
#define PQ 24            // P + Q

// Output layout (tuple flattened, row-major each):
//  Y       (B,1,H,W,1)       4096   @ 0
//  x       (B,P,H,W,1)      49152   @ 4096
//  trans   (B,P,H,W,8,1)   393216   @ 53248
//  restart (B,P,H,W,1)      49152   @ 446464
//  results (B,P,H,W,1,13)  638976   @ 495616
#define OFF_Y    0
#define OFF_X    4096
#define OFF_T    53248
#define OFF_R    446464
#define OFF_RES  495616

__global__ __launch_bounds__(1024, 1) void rwr_kernel(
    const float* __restrict__ X,
    const int*   __restrict__ TE,
    const float* __restrict__ Wt,   // (1192, 8)
    const float* __restrict__ Wr,   // (1192, 1)
    const float* __restrict__ Wb,   // (1192, 1)
    float*       __restrict__ out)
{
    const int bp   = blockIdx.x;        // 0..47
    const int b    = bp / PP;
    const int p    = bp % PP;
    const int cell = threadIdx.x;       // 0..1023
    const int h    = cell >> 5;
    const int w    = cell & 31;

    // tp: padded trans-prob planes (one-time incoming-weight gather),
    //     later reused as results staging buffer (9248 floats >= 6656 per half).
    // xs: double-buffered padded x tile.
    __shared__ __align__(16) float tp[8][34][34];   // 36992 B
    __shared__ __align__(16) float xs[2][34][34];   //  9248 B

    // ---- prefetch all globals up front (MLP) ----
    const float x0 = X[bp * NUM_CELLS + cell];
    const int te_day  = TE[(b * PQ + p) * 2 + 0];
    const int te_hour = TE[(b * PQ + p) * 2 + 1];
    const int te = te_day * 24 + te_hour;            // < 168
    const int cr = TE_DEPTH + cell;

    const float4* wc4 = reinterpret_cast<const float4*>(Wt + (size_t)cr * 8);
    const float4 wc_lo = wc4[0];
    const float4 wc_hi = wc4[1];
    const float4* wt4 = reinterpret_cast<const float4*>(Wt + (size_t)te * 8);
    const float4 wt_lo = wt4[0];
    const float4 wt_hi = wt4[1];
    const float wr_te = Wr[te], wr_c = Wr[cr];
    const float wb_te = Wb[te], wb_c = Wb[cr];

    // ---- zero tp fully via float4 (borders must be 0; interior overwritten) ----
    {
        float4* tpf = reinterpret_cast<float4*>(&tp[0][0][0]);
        #pragma unroll
        for (int i = 0; i < 3; i++) {
            int idx = cell + i * 1024;
            if (idx < 2312) tpf[idx] = make_float4(0.f, 0.f, 0.f, 0.f);
        }
    }
    // ---- zero only the perimeter of xs (132 cells per buffer, 2 buffers) ----
    if (cell < 264) {
        const int bufb = cell / 132;
        const int j = cell % 132;
        int rr, cc;
        if      (j <  34) { rr = 0;       cc = j; }
        else if (j <  68) { rr = 33;      cc = j - 34; }
        else if (j < 100) { rr = j - 67;  cc = 0;  }   // rows 1..32
        else              { rr = j - 99;  cc = 33; }   // rows 1..32
        xs[bufb][rr][cc] = 0.f;
    }

    // ---- softmax over 8 dirs (fast math; logits are tiny, skip max-sub) ----
    float lg[8];
    lg[0] = wt_lo.x + wc_lo.x;  lg[1] = wt_lo.y + wc_lo.y;
    lg[2] = wt_lo.z + wc_lo.z;  lg[3] = wt_lo.w + wc_lo.w;
    lg[4] = wt_hi.x + wc_hi.x;  lg[5] = wt_hi.y + wc_hi.y;
    lg[6] = wt_hi.z + wc_hi.z;  lg[7] = wt_hi.w + wc_hi.w;
    float e[8], s = 0.f;
    #pragma unroll
    for (int d = 0; d < 8; d++) { e[d] = __expf(lg[d]); s += e[d]; }
    const float inv_s = __fdividef(1.0f, s);
    float tpv[8];
    #pragma unroll
    for (int d = 0; d < 8; d++) tpv[d] = e[d] * inv_s;

    // restart (sigmoid) and bias
    const float rz = wr_te + wr_c;
    const float restart = __fdividef(1.0f, 1.0f + __expf(-rz));
    const float one_m_r = 1.0f - restart;
    const float bias = (wb_te + wb_c) * x0;

    // ---- static outputs ----
    {
        float4* t4 = reinterpret_cast<float4*>(out + OFF_T + (size_t)(bp * NUM_CELLS + cell) * 8);
        t4[0] = make_float4(tpv[0], tpv[1], tpv[2], tpv[3]);
        t4[1] = make_float4(tpv[4], tpv[5], tpv[6], tpv[7]);
    }
    out[OFF_R + bp * NUM_CELLS + cell] = restart;

    __syncthreads();   // tp zero complete before interior fill
    #pragma unroll
    for (int j = 0; j < 8; j++) tp[j][h + 1][w + 1] = tpv[j];
    __syncthreads();   // tp filled (+ xs perimeter zeroed)

    // DIRS d: 0:(-1,-1) 1:(-1,0) 2:(-1,1) 3:(0,-1) 4:(0,1) 5:(1,-1) 6:(1,0) 7:(1,1)
    const int DR[8] = {-1,-1,-1, 0, 0, 1, 1, 1};
    const int DC[8] = {-1, 0, 1,-1, 1,-1, 0, 1};

    // incoming weight from neighbor (h+dr, w+dc) via channel d
    float w_in[8];
    #pragma unroll
    for (int d = 0; d < 8; d++)
        w_in[d] = tp[d][h + 1 + DR[d]][w + 1 + DC[d]];

    // ---- iterate; keep per-step results in registers ----
    float r[KSTEP + 1];
    float x = x0;
    r[0] = x0;

    #pragma unroll
    for (int k = 0; k < KSTEP; k++) {
        const int buf = k & 1;
        xs[buf][h + 1][w + 1] = x;
        __syncthreads();
        float a0 = xs[buf][h    ][w    ] * w_in[0];
        float a1 = xs[buf][h    ][w + 1] * w_in[1];
        float a2 = xs[buf][h    ][w + 2] * w_in[2];
        float a3 = xs[buf][h + 1][w    ] * w_in[3];
        a0 = fmaf(xs[buf][h + 1][w + 2], w_in[4], a0);
        a1 = fmaf(xs[buf][h + 2][w    ], w_in[5], a1);
        a2 = fmaf(xs[buf][h + 2][w + 1], w_in[6], a2);
        a3 = fmaf(xs[buf][h + 2][w + 2], w_in[7], a3);
        const float xt = (a0 + a1) + (a2 + a3);
        x = fmaf(one_m_r, xt, fmaf(restart, x, bias));
        r[k + 1] = x;
    }

    // final state x (coalesced) + Y
    out[OFF_X + bp * NUM_CELLS + cell] = x;
    if (p == PP - 1)
        out[OFF_Y + b * NUM_CELLS + cell] = x;

    // ---- coalesced results dump: stage through tp, 2 halves of 512 cells ----
    float* stage = &tp[0][0][0];
    #pragma unroll
    for (int hf = 0; hf < 2; hf++) {
        __syncthreads();   // previous readers of stage done
        if ((cell >> 9) == hf) {
            const int lc = cell & 511;
            #pragma unroll
            for (int k = 0; k <= KSTEP; k++)
                stage[lc * 13 + k] = r[k];     // odd stride -> conflict-free
        }
        __syncthreads();
        const float4* s4 = reinterpret_cast<const float4*>(stage);
        float4* o4 = reinterpret_cast<float4*>(
            out + OFF_RES + (size_t)bp * (NUM_CELLS * 13) + hf * (512 * 13));
        #pragma unroll
        for (int i = 0; i < 2; i++) {
            int idx = cell + i * 1024;
            if (idx < 1664) o4[idx] = s4[idx];
        }
    }
}

extern "C" void kernel_launch(void* const* d_in, const int* in_sizes, int n_in,
                              void* d_out, int out_size) {
    const float* X  = (const float*)d_in[0];
    const int*   TE = (const int*)d_in[1];
    const float* Wt = (const float*)d_in[2];
    const float* Wr = (const float*)d_in[3];
    const float* Wb = (const float*)d_in[4];
    float* out = (float*)d_out;
    rwr_kernel<<<BB * PP, 1024>>>(X, TE, Wt, Wr, Wb, out);
}